// round 2
// baseline (speedup 1.0000x reference)
#include <cuda_runtime.h>
#include <math.h>

// ---------------------------------------------------------------------------
// FCOS head, fp32 direct conv baseline.
//   - conv3x3 256->256 tiled: 64 oc x 64 px (8x8) per block, 4x4 reg tile,
//     8-input-channel smem chunks. GN stats (sum/sumsq per (b,group))
//     accumulated via per-warp reduce + global atomics inside the conv.
//   - GN apply + ReLU fused into the NEXT conv's input load as per-channel
//     affine (a*x+s, relu), computed by a tiny finalize kernel.
//   - Head convs (80/1/4 oc) write straight into d_out final layout.
// ---------------------------------------------------------------------------

#define MAXBUF (8*256*15200)   // level-0 activation tensor, floats

__device__ float g_buf0[MAXBUF];
__device__ float g_buf1[MAXBUF];
__device__ float g_buf2[MAXBUF];
__device__ float g_buf3[MAXBUF];
__device__ float g_stats[8*32*2];
__device__ float g_aff[2][2][8*256];   // [slot cls/box][A or S][b*256+c]

// ---------------------------------------------------------------------------
// Tower conv: IC=256, OC=256 (4 oc-blocks of 64), 3x3 SAME, + bias,
// + per-(b,group) sum/sumsq atomics. Optional input affine+relu.
// ---------------------------------------------------------------------------
template<bool AFF>
__global__ __launch_bounds__(256) void conv256(
    const float* __restrict__ x, const float* __restrict__ w,
    const float* __restrict__ bias,
    const float* __restrict__ affA, const float* __restrict__ affS,
    float* __restrict__ y, float* __restrict__ stats, int H, int W)
{
    const int HW = H * W;
    const int b   = blockIdx.z >> 2;
    const int ocb = blockIdx.z & 3;
    const int h0  = blockIdx.y << 3;
    const int w0  = blockIdx.x << 3;
    const int tid = threadIdx.x;
    const int lane_px = tid & 15;   // 16 px slots, each owns px {s, s+16, s+32, s+48}
    const int lane_oc = tid >> 4;   // 16 oc slots, each owns 4 consecutive oc
    const int oc0 = (ocb << 6) + (lane_oc << 2);

    __shared__ float s_in[8][10][12];
    __shared__ float s_w[8][9][64];

    float acc[4][4];
    #pragma unroll
    for (int i = 0; i < 4; i++)
        #pragma unroll
        for (int j = 0; j < 4; j++) acc[i][j] = 0.f;

    const float* xb = x + (size_t)b * 256 * HW;
    const float* aA = AFF ? (affA + b * 256) : nullptr;
    const float* aS = AFF ? (affS + b * 256) : nullptr;

    const int ph_base = lane_px >> 3;   // 0/1
    const int pw      = lane_px & 7;

    for (int c0 = 0; c0 < 256; c0 += 8) {
        // ---- load input chunk: 8 ic x 10 x 10 (zero-padded borders) ----
        for (int idx = tid; idx < 800; idx += 256) {
            int ic = idx / 100; int rr = idx - ic * 100;
            int r = rr / 10;    int c  = rr - r * 10;
            int ih = h0 - 1 + r, iw = w0 - 1 + c;
            float v = 0.f;
            if ((unsigned)ih < (unsigned)H && (unsigned)iw < (unsigned)W) {
                v = xb[(size_t)(c0 + ic) * HW + ih * W + iw];
                if (AFF) v = fmaxf(fmaf(aA[c0 + ic], v, aS[c0 + ic]), 0.f);
            }
            s_in[ic][r][c] = v;
        }
        // ---- load weights: 64 oc x 8 ic x 9, transposed to [ic][k][oc] ----
        const float* wp = w + (size_t)(ocb * 64) * 2304 + c0 * 9;
        for (int idx = tid; idx < 4608; idx += 256) {
            int oc = idx / 72; int rem = idx - oc * 72;
            int ic = rem / 9;  int k   = rem - ic * 9;
            s_w[ic][k][oc] = wp[(size_t)oc * 2304 + ic * 9 + k];
        }
        __syncthreads();

        #pragma unroll 4
        for (int ic = 0; ic < 8; ic++) {
            #pragma unroll
            for (int kh = 0; kh < 3; kh++) {
                #pragma unroll
                for (int kw = 0; kw < 3; kw++) {
                    float4 wv = *(const float4*)&s_w[ic][kh * 3 + kw][lane_oc << 2];
                    float xv0 = s_in[ic][ph_base + 0 + kh][pw + kw];
                    float xv1 = s_in[ic][ph_base + 2 + kh][pw + kw];
                    float xv2 = s_in[ic][ph_base + 4 + kh][pw + kw];
                    float xv3 = s_in[ic][ph_base + 6 + kh][pw + kw];
                    acc[0][0] = fmaf(wv.x, xv0, acc[0][0]);
                    acc[0][1] = fmaf(wv.x, xv1, acc[0][1]);
                    acc[0][2] = fmaf(wv.x, xv2, acc[0][2]);
                    acc[0][3] = fmaf(wv.x, xv3, acc[0][3]);
                    acc[1][0] = fmaf(wv.y, xv0, acc[1][0]);
                    acc[1][1] = fmaf(wv.y, xv1, acc[1][1]);
                    acc[1][2] = fmaf(wv.y, xv2, acc[1][2]);
                    acc[1][3] = fmaf(wv.y, xv3, acc[1][3]);
                    acc[2][0] = fmaf(wv.z, xv0, acc[2][0]);
                    acc[2][1] = fmaf(wv.z, xv1, acc[2][1]);
                    acc[2][2] = fmaf(wv.z, xv2, acc[2][2]);
                    acc[2][3] = fmaf(wv.z, xv3, acc[2][3]);
                    acc[3][0] = fmaf(wv.w, xv0, acc[3][0]);
                    acc[3][1] = fmaf(wv.w, xv1, acc[3][1]);
                    acc[3][2] = fmaf(wv.w, xv2, acc[3][2]);
                    acc[3][3] = fmaf(wv.w, xv3, acc[3][3]);
                }
            }
        }
        __syncthreads();
    }

    // ---- epilogue: bias, store, per-warp GN stats ----
    float lsum = 0.f, lsq = 0.f;
    #pragma unroll
    for (int i = 0; i < 4; i++) {
        int oc = oc0 + i;
        float bv = bias[oc];
        #pragma unroll
        for (int j = 0; j < 4; j++) {
            int p  = lane_px + (j << 4);
            int hh = h0 + (p >> 3), ww = w0 + (p & 7);
            if (hh < H && ww < W) {
                float v = acc[i][j] + bv;
                y[(size_t)(b * 256 + oc) * HW + hh * W + ww] = v;
                lsum += v; lsq += v * v;
            }
        }
    }
    // Entire warp maps to one GN group (4-aligned oc runs of 4 in 8-wide groups).
    #pragma unroll
    for (int off = 16; off; off >>= 1) {
        lsum += __shfl_xor_sync(0xffffffffu, lsum, off);
        lsq  += __shfl_xor_sync(0xffffffffu, lsq,  off);
    }
    if ((tid & 31) == 0) {
        int g = (ocb << 3) + (lane_oc >> 1);
        atomicAdd(&stats[(b * 32 + g) * 2 + 0], lsum);
        atomicAdd(&stats[(b * 32 + g) * 2 + 1], lsq);
    }
}

// ---------------------------------------------------------------------------
// GN finalize: stats -> per-channel affine (a, s); relu applied downstream.
// ---------------------------------------------------------------------------
__global__ void gn_finalize(const float* __restrict__ stats,
                            const float* __restrict__ gamma,
                            const float* __restrict__ beta,
                            float* __restrict__ affA, float* __restrict__ affS,
                            float invCnt)
{
    int b = blockIdx.x;
    int c = threadIdx.x;      // 256
    int g = c >> 3;
    float sum = stats[(b * 32 + g) * 2 + 0];
    float sq  = stats[(b * 32 + g) * 2 + 1];
    float m   = sum * invCnt;
    float var = fmaf(sq, invCnt, -m * m);
    float rstd = rsqrtf(var + 1e-5f);
    float a = gamma[c] * rstd;
    affA[b * 256 + c] = a;
    affS[b * 256 + c] = fmaf(-m, a, beta[c]);
}

// ---------------------------------------------------------------------------
// Head conv: IC=256, OC in {80,1,4}. Input affine+relu always. Writes directly
// into d_out at [b*TOT + lvlOff + (cbase+oc)*HW + h*W + w]; optional exp(scale*).
// ---------------------------------------------------------------------------
__global__ __launch_bounds__(256) void conv_head(
    const float* __restrict__ x, const float* __restrict__ w,
    const float* __restrict__ bias,
    const float* __restrict__ affA, const float* __restrict__ affS,
    float* __restrict__ out, size_t lvlOff, size_t TOT, int cbase,
    int OC, int H, int W, int doExp, const float* __restrict__ scales, int lvl)
{
    const int HW = H * W;
    const int b  = blockIdx.z;
    const int h0 = blockIdx.y << 3, w0 = blockIdx.x << 3;
    const int tid  = threadIdx.x;
    const int lane = tid & 3;      // 4 oc lanes
    const int p    = tid >> 2;     // 64 px slots, 1 px each
    const int ph = p >> 3, pw = p & 7;

    __shared__ float s_in[8][10][12];
    __shared__ float s_w[8][9][80];

    float acc[20];
    const int noc = (OC + 3) >> 2;
    #pragma unroll
    for (int j = 0; j < 20; j++) acc[j] = 0.f;

    const float* xb = x + (size_t)b * 256 * HW;
    const float* aA = affA + b * 256;
    const float* aS = affS + b * 256;

    for (int c0 = 0; c0 < 256; c0 += 8) {
        for (int idx = tid; idx < 800; idx += 256) {
            int ic = idx / 100; int rr = idx - ic * 100;
            int r = rr / 10;    int c  = rr - r * 10;
            int ih = h0 - 1 + r, iw = w0 - 1 + c;
            float v = 0.f;
            if ((unsigned)ih < (unsigned)H && (unsigned)iw < (unsigned)W) {
                v = xb[(size_t)(c0 + ic) * HW + ih * W + iw];
                v = fmaxf(fmaf(aA[c0 + ic], v, aS[c0 + ic]), 0.f);
            }
            s_in[ic][r][c] = v;
        }
        int nw = OC * 72;
        for (int idx = tid; idx < nw; idx += 256) {
            int oc = idx / 72; int rem = idx - oc * 72;
            int ic = rem / 9;  int k   = rem - ic * 9;
            s_w[ic][k][oc] = w[(size_t)oc * 2304 + (c0 + ic) * 9 + k];
        }
        __syncthreads();

        #pragma unroll 2
        for (int ic = 0; ic < 8; ic++) {
            #pragma unroll
            for (int kh = 0; kh < 3; kh++) {
                #pragma unroll
                for (int kw = 0; kw < 3; kw++) {
                    float xv = s_in[ic][ph + kh][pw + kw];
                    int k = kh * 3 + kw;
                    for (int j = 0; j < noc; j++)
                        acc[j] = fmaf(xv, s_w[ic][k][(j << 2) + lane], acc[j]);
                }
            }
        }
        __syncthreads();
    }

    int hh = h0 + ph, ww = w0 + pw;
    if (hh < H && ww < W) {
        float sc = doExp ? scales[lvl] : 0.f;
        for (int j = 0; j < noc; j++) {
            int oc = (j << 2) + lane;
            if (oc < OC) {
                float v = acc[j] + bias[oc];
                if (doExp) v = expf(sc * v);
                out[(size_t)b * TOT + lvlOff + (size_t)(cbase + oc) * HW + hh * W + ww] = v;
            }
        }
    }
}

// ---------------------------------------------------------------------------
// FCOS grid locations, appended after the head outputs.
// ---------------------------------------------------------------------------
__global__ void locations_kernel(float* __restrict__ out, size_t base)
{
    const int Wl[5] = {152, 76, 38, 19, 10};
    const int Sl[5] = {8, 16, 32, 64, 128};
    const int sizes[5] = {15200, 3800, 950, 247, 70};
    int idx = blockIdx.x * blockDim.x + threadIdx.x;
    if (idx >= 20267) return;
    int l = 0, t = idx;
    while (l < 4 && t >= sizes[l]) { t -= sizes[l]; l++; }
    int yy = t / Wl[l], xx = t - yy * Wl[l];
    out[base + (size_t)idx * 2 + 0] = (float)(xx * Sl[l] + Sl[l] / 2);
    out[base + (size_t)idx * 2 + 1] = (float)(yy * Sl[l] + Sl[l] / 2);
}

// ---------------------------------------------------------------------------
// Host orchestration
// ---------------------------------------------------------------------------
extern "C" void kernel_launch(void* const* d_in, const int* in_sizes, int n_in,
                              void* d_out, int out_size)
{
    const float* feats[5] = {
        (const float*)d_in[0], (const float*)d_in[1], (const float*)d_in[2],
        (const float*)d_in[3], (const float*)d_in[4]};
    const float* cls_w    = (const float*)d_in[5];
    const float* cls_b    = (const float*)d_in[6];
    const float* cls_gn_g = (const float*)d_in[7];
    const float* cls_gn_b = (const float*)d_in[8];
    const float* box_w    = (const float*)d_in[9];
    const float* box_b    = (const float*)d_in[10];
    const float* box_gn_g = (const float*)d_in[11];
    const float* box_gn_b = (const float*)d_in[12];
    const float* logits_w = (const float*)d_in[13];
    const float* logits_b = (const float*)d_in[14];
    const float* ctr_w    = (const float*)d_in[15];
    const float* ctr_b    = (const float*)d_in[16];
    const float* reg_w    = (const float*)d_in[17];
    const float* reg_b    = (const float*)d_in[18];
    const float* scales   = (const float*)d_in[19];

    float *buf0, *buf1, *buf2, *buf3, *stats, *aff;
    cudaGetSymbolAddress((void**)&buf0, g_buf0);
    cudaGetSymbolAddress((void**)&buf1, g_buf1);
    cudaGetSymbolAddress((void**)&buf2, g_buf2);
    cudaGetSymbolAddress((void**)&buf3, g_buf3);
    cudaGetSymbolAddress((void**)&stats, g_stats);
    cudaGetSymbolAddress((void**)&aff, g_aff);
    float* affA0 = aff;               // [2][2][2048]
    float* affS0 = aff + 2048;
    float* affA1 = aff + 4096;
    float* affS1 = aff + 6144;

    float* out = (float*)d_out;

    const int Hs[5] = {100, 50, 25, 13, 7};
    const int Ws[5] = {152, 76, 38, 19, 10};
    const size_t off85[5] = {0, 1292000, 1615000, 1695750, 1716745};
    const size_t TOT = 1722695;                 // 85 * 20267

    for (int l = 0; l < 5; l++) {
        const int H = Hs[l], W = Ws[l], HW = H * W;
        dim3 grid((W + 7) / 8, (H + 7) / 8, 8 * 4);
        dim3 gridH((W + 7) / 8, (H + 7) / 8, 8);
        const float invCnt = 1.0f / (8.0f * (float)HW);

        // ---- cls tower (buf0/buf1, affine slot 0) ----
        {
            const float* cur = feats[l];
            float* bufs[2] = {buf0, buf1};
            for (int i = 0; i < 4; i++) {
                const float* wi = cls_w + (size_t)i * 256 * 2304;
                const float* bi = cls_b + i * 256;
                cudaMemsetAsync(stats, 0, 8 * 32 * 2 * sizeof(float), 0);
                if (i == 0)
                    conv256<false><<<grid, 256>>>(cur, wi, bi, nullptr, nullptr,
                                                  bufs[i & 1], stats, H, W);
                else
                    conv256<true><<<grid, 256>>>(cur, wi, bi, affA0, affS0,
                                                 bufs[i & 1], stats, H, W);
                gn_finalize<<<8, 256>>>(stats, cls_gn_g + i * 256, cls_gn_b + i * 256,
                                        affA0, affS0, invCnt);
                cur = bufs[i & 1];
            }
        }
        const float* ct = buf1;   // layer 3 wrote bufs[1]

        // ---- box tower (buf2/buf3, affine slot 1) ----
        {
            const float* cur = feats[l];
            float* bufs[2] = {buf2, buf3};
            for (int i = 0; i < 4; i++) {
                const float* wi = box_w + (size_t)i * 256 * 2304;
                const float* bi = box_b + i * 256;
                cudaMemsetAsync(stats, 0, 8 * 32 * 2 * sizeof(float), 0);
                if (i == 0)
                    conv256<false><<<grid, 256>>>(cur, wi, bi, nullptr, nullptr,
                                                  bufs[i & 1], stats, H, W);
                else
                    conv256<true><<<grid, 256>>>(cur, wi, bi, affA1, affS1,
                                                 bufs[i & 1], stats, H, W);
                gn_finalize<<<8, 256>>>(stats, box_gn_g + i * 256, box_gn_b + i * 256,
                                        affA1, affS1, invCnt);
                cur = bufs[i & 1];
            }
        }
        const float* bt = buf3;

        // ---- heads: logits(80)@c0, reg(4)@c80 (exp), ctr(1)@c84 ----
        conv_head<<<gridH, 256>>>(ct, logits_w, logits_b, affA0, affS0,
                                  out, off85[l], TOT, 0, 80, H, W, 0, scales, l);
        conv_head<<<gridH, 256>>>(bt, reg_w, reg_b, affA1, affS1,
                                  out, off85[l], TOT, 80, 4, H, W, 1, scales, l);
        conv_head<<<gridH, 256>>>(ct, ctr_w, ctr_b, affA0, affS0,
                                  out, off85[l], TOT, 84, 1, H, W, 0, scales, l);
    }

    locations_kernel<<<(20267 + 255) / 256, 256>>>(out, (size_t)8 * TOT);
}

// round 4
// speedup vs baseline: 1.2456x; 1.2456x over previous
#include <cuda_runtime.h>
#include <math.h>

// ---------------------------------------------------------------------------
// FCOS head, fp32 with packed f32x2 FFMA (Blackwell FFMA2) tower convs.
//  - conv3x3 256->256: 64 oc x 128 px (8x16) per block, pixels paired (w,w+8)
//    into f32x2. Inner loop: LDS.64 x-pairs + LDS.128 dup-weight pairs ->
//    fma.rn.f32x2. 8-ic smem chunks.
//  - Weights pre-reshaped once per launch into duplicated-pair smem layout
//    so the per-chunk weight fill is a straight coalesced copy.
//  - GN stats via per-warp reduce + atomics in conv epilogue; GN apply + ReLU
//    fused into next conv's input load as per-channel affine.
//  - Head convs write directly into d_out final layout.
// ---------------------------------------------------------------------------

typedef unsigned long long ull;

#define MAXBUF (8*256*15200)   // level-0 activation tensor, floats

__device__ float g_buf0[MAXBUF];
__device__ float g_buf1[MAXBUF];
__device__ float g_buf2[MAXBUF];
__device__ float g_buf3[MAXBUF];
__device__ float g_stats[8*32*2];
__device__ float g_aff[2][2][8*256];          // [slot][A|S][b*256+c]
__device__ ull   g_wrs[8*4*32*72*64];         // 8 layers (4 cls + 4 box), dup pairs

__device__ __forceinline__ void fma2(ull& d, ull a, ull b) {
    asm("fma.rn.f32x2 %0, %1, %2, %0;" : "+l"(d) : "l"(a), "l"(b));
}
__device__ __forceinline__ float lo32(ull v) { return __uint_as_float((unsigned)v); }
__device__ __forceinline__ float hi32(ull v) { return __uint_as_float((unsigned)(v >> 32)); }
__device__ __forceinline__ ull pack2(float lo, float hi) {
    ull u; asm("mov.b64 %0, {%1, %2};" : "=l"(u) : "f"(lo), "f"(hi)); return u;
}

// ---------------------------------------------------------------------------
// Weight reshape: w[lay][oc][ic*9+k] -> g_wrs[lay][ocb][chunk][(ic8*9+k)*64+oc64]
// as duplicated (w,w) f32x2 pairs. lay 0-3 = cls, 4-7 = box.
// ---------------------------------------------------------------------------
__global__ void reshape_weights(const float* __restrict__ cls_w,
                                const float* __restrict__ box_w,
                                ull* __restrict__ out)
{
    int idx = blockIdx.x * blockDim.x + threadIdx.x;      // 4,718,592 total
    if (idx >= 8*4*32*72*64) return;
    int oc  = idx & 63;  int t = idx >> 6;
    int k   = t % 9;     t /= 9;
    int ic  = t & 7;     t >>= 3;
    int chunk = t & 31;  t >>= 5;
    int ocb = t & 3;     int lay = t >> 2;
    const float* src = (lay < 4) ? cls_w : box_w;
    int l = lay & 3;
    float w = src[(size_t)l * 256 * 2304 + (size_t)(ocb * 64 + oc) * 2304
                  + (chunk * 8 + ic) * 9 + k];
    out[idx] = pack2(w, w);
}

// ---------------------------------------------------------------------------
// Tower conv, f32x2 packed. 64 oc x (8h x 16w) px per block. 256 threads:
// lane_oc = tid>>4 (16 slots x 4 oc), lane_px = tid&15 (16 pair-slots x 4 pairs).
// Pair p (p = r*8+cp) covers pixels (h0+r, w0+cp) and (h0+r, w0+cp+8).
// ---------------------------------------------------------------------------
template<bool AFF>
__global__ __launch_bounds__(256) void conv256p(
    const float* __restrict__ x, const ull* __restrict__ wlay,
    const float* __restrict__ bias,
    const float* __restrict__ affA, const float* __restrict__ affS,
    float* __restrict__ y, float* __restrict__ stats, int H, int W)
{
    const int HW  = H * W;
    const int b   = blockIdx.z >> 2;
    const int ocb = blockIdx.z & 3;
    const int h0  = blockIdx.y << 3;
    const int w0  = blockIdx.x << 4;
    const int tid = threadIdx.x;
    const int lane_px = tid & 15;
    const int lane_oc = tid >> 4;
    const int oc0 = (ocb << 6) + (lane_oc << 2);
    const int r0  = lane_px >> 3;          // 0/1
    const int cp  = lane_px & 7;           // 0..7

    __shared__ ull s_w[8 * 9 * 64];        // 36864 B, dup pairs [ic*9+k][oc]
    __shared__ ull s_in[8][10][10];        // 6400 B, pairs (c, c+8)

    ull acc[4][4];
    #pragma unroll
    for (int i = 0; i < 4; i++)
        #pragma unroll
        for (int j = 0; j < 4; j++) acc[i][j] = 0ull;

    const float* xb = x + (size_t)b * 256 * HW;
    const float* aA = AFF ? (affA + b * 256) : nullptr;
    const float* aS = AFF ? (affS + b * 256) : nullptr;

    for (int chunk = 0; chunk < 32; chunk++) {
        const int c0 = chunk << 3;
        // ---- input pairs: 8 ic x 10r x 10c, components (iw, iw+8) ----
        for (int idx = tid; idx < 800; idx += 256) {
            int ic = idx / 100; int rr = idx - ic * 100;
            int r  = rr / 10;   int c  = rr - r * 10;
            int ih  = h0 - 1 + r;
            int iw0 = w0 - 1 + c;
            int iw1 = iw0 + 8;
            float v0 = 0.f, v1 = 0.f;
            if ((unsigned)ih < (unsigned)H) {
                const float* row = xb + (size_t)(c0 + ic) * HW + (size_t)ih * W;
                if ((unsigned)iw0 < (unsigned)W) {
                    v0 = row[iw0];
                    if (AFF) v0 = fmaxf(fmaf(aA[c0 + ic], v0, aS[c0 + ic]), 0.f);
                }
                if ((unsigned)iw1 < (unsigned)W) {
                    v1 = row[iw1];
                    if (AFF) v1 = fmaxf(fmaf(aA[c0 + ic], v1, aS[c0 + ic]), 0.f);
                }
            }
            s_in[ic][r][c] = pack2(v0, v1);
        }
        // ---- weights: straight coalesced copy of 4608 ull ----
        const ull* wseg = wlay + ((size_t)ocb * 32 + chunk) * 4608;
        #pragma unroll
        for (int t = 0; t < 18; t++)
            s_w[t * 256 + tid] = wseg[t * 256 + tid];
        __syncthreads();

        for (int ic = 0; ic < 8; ic++) {
            #pragma unroll
            for (int k = 0; k < 9; k++) {
                const int kh = k / 3, kw = k - kh * 3;
                const ull* wp = &s_w[(ic * 9 + k) * 64 + (lane_oc << 2)];
                ull w0v = wp[0], w1v = wp[1], w2v = wp[2], w3v = wp[3];
                ull xv0 = s_in[ic][r0 + 0 + kh][cp + kw];
                ull xv1 = s_in[ic][r0 + 2 + kh][cp + kw];
                ull xv2 = s_in[ic][r0 + 4 + kh][cp + kw];
                ull xv3 = s_in[ic][r0 + 6 + kh][cp + kw];
                fma2(acc[0][0], w0v, xv0); fma2(acc[0][1], w0v, xv1);
                fma2(acc[0][2], w0v, xv2); fma2(acc[0][3], w0v, xv3);
                fma2(acc[1][0], w1v, xv0); fma2(acc[1][1], w1v, xv1);
                fma2(acc[1][2], w1v, xv2); fma2(acc[1][3], w1v, xv3);
                fma2(acc[2][0], w2v, xv0); fma2(acc[2][1], w2v, xv1);
                fma2(acc[2][2], w2v, xv2); fma2(acc[2][3], w2v, xv3);
                fma2(acc[3][0], w3v, xv0); fma2(acc[3][1], w3v, xv1);
                fma2(acc[3][2], w3v, xv2); fma2(acc[3][3], w3v, xv3);
            }
        }
        __syncthreads();
    }

    // ---- epilogue: bias, store, per-warp GN stats ----
    float lsum = 0.f, lsq = 0.f;
    #pragma unroll
    for (int i = 0; i < 4; i++) {
        const int oc = oc0 + i;
        const float bv = bias[oc];
        float* yb = y + (size_t)(b * 256 + oc) * HW;
        #pragma unroll
        for (int j = 0; j < 4; j++) {
            const int r  = r0 + (j << 1);
            const int hh = h0 + r;
            const int wl = w0 + cp;
            const int wh = wl + 8;
            float vl = lo32(acc[i][j]) + bv;
            float vh = hi32(acc[i][j]) + bv;
            if (hh < H && wl < W) { yb[(size_t)hh * W + wl] = vl; lsum += vl; lsq += vl * vl; }
            if (hh < H && wh < W) { yb[(size_t)hh * W + wh] = vh; lsum += vh; lsq += vh * vh; }
        }
    }
    // warp = lane_oc pair {2t,2t+1} -> 8 consecutive oc -> exactly one GN group
    #pragma unroll
    for (int off = 16; off; off >>= 1) {
        lsum += __shfl_xor_sync(0xffffffffu, lsum, off);
        lsq  += __shfl_xor_sync(0xffffffffu, lsq,  off);
    }
    if ((tid & 31) == 0) {
        int g = (ocb << 3) + (lane_oc >> 1);
        atomicAdd(&stats[(b * 32 + g) * 2 + 0], lsum);
        atomicAdd(&stats[(b * 32 + g) * 2 + 1], lsq);
    }
}

// ---------------------------------------------------------------------------
// GN finalize: stats -> per-channel affine (a, s).
// ---------------------------------------------------------------------------
__global__ void gn_finalize(const float* __restrict__ stats,
                            const float* __restrict__ gamma,
                            const float* __restrict__ beta,
                            float* __restrict__ affA, float* __restrict__ affS,
                            float invCnt)
{
    int b = blockIdx.x;
    int c = threadIdx.x;      // 256
    int g = c >> 3;
    float sum = stats[(b * 32 + g) * 2 + 0];
    float sq  = stats[(b * 32 + g) * 2 + 1];
    float m   = sum * invCnt;
    float var = fmaf(sq, invCnt, -m * m);
    float rstd = rsqrtf(var + 1e-5f);
    float a = gamma[c] * rstd;
    affA[b * 256 + c] = a;
    affS[b * 256 + c] = fmaf(-m, a, beta[c]);
}

// ---------------------------------------------------------------------------
// Head conv: IC=256, OC in {80,1,4}. Affine+relu input. Direct final layout.
// ---------------------------------------------------------------------------
__global__ __launch_bounds__(256) void conv_head(
    const float* __restrict__ x, const float* __restrict__ w,
    const float* __restrict__ bias,
    const float* __restrict__ affA, const float* __restrict__ affS,
    float* __restrict__ out, size_t lvlOff, size_t TOT, int cbase,
    int OC, int H, int W, int doExp, const float* __restrict__ scales, int lvl)
{
    const int HW = H * W;
    const int b  = blockIdx.z;
    const int h0 = blockIdx.y << 3, w0 = blockIdx.x << 3;
    const int tid  = threadIdx.x;
    const int lane = tid & 3;      // 4 oc lanes
    const int p    = tid >> 2;     // 64 px slots
    const int ph = p >> 3, pw = p & 7;

    __shared__ float s_in[8][10][12];
    __shared__ float s_w[8][9][80];

    float acc[20];
    const int noc = (OC + 3) >> 2;
    #pragma unroll
    for (int j = 0; j < 20; j++) acc[j] = 0.f;

    const float* xb = x + (size_t)b * 256 * HW;
    const float* aA = affA + b * 256;
    const float* aS = affS + b * 256;

    for (int c0 = 0; c0 < 256; c0 += 8) {
        for (int idx = tid; idx < 800; idx += 256) {
            int ic = idx / 100; int rr = idx - ic * 100;
            int r = rr / 10;    int c  = rr - r * 10;
            int ih = h0 - 1 + r, iw = w0 - 1 + c;
            float v = 0.f;
            if ((unsigned)ih < (unsigned)H && (unsigned)iw < (unsigned)W) {
                v = xb[(size_t)(c0 + ic) * HW + ih * W + iw];
                v = fmaxf(fmaf(aA[c0 + ic], v, aS[c0 + ic]), 0.f);
            }
            s_in[ic][r][c] = v;
        }
        int nw = OC * 72;
        for (int idx = tid; idx < nw; idx += 256) {
            int oc = idx / 72; int rem = idx - oc * 72;
            int ic = rem / 9;  int k   = rem - ic * 9;
            s_w[ic][k][oc] = w[(size_t)oc * 2304 + (c0 + ic) * 9 + k];
        }
        __syncthreads();

        #pragma unroll 2
        for (int ic = 0; ic < 8; ic++) {
            #pragma unroll
            for (int kh = 0; kh < 3; kh++) {
                #pragma unroll
                for (int kw = 0; kw < 3; kw++) {
                    float xv = s_in[ic][ph + kh][pw + kw];
                    int k = kh * 3 + kw;
                    for (int j = 0; j < noc; j++)
                        acc[j] = fmaf(xv, s_w[ic][k][(j << 2) + lane], acc[j]);
                }
            }
        }
        __syncthreads();
    }

    int hh = h0 + ph, ww = w0 + pw;
    if (hh < H && ww < W) {
        float sc = doExp ? scales[lvl] : 0.f;
        for (int j = 0; j < noc; j++) {
            int oc = (j << 2) + lane;
            if (oc < OC) {
                float v = acc[j] + bias[oc];
                if (doExp) v = expf(sc * v);
                out[(size_t)b * TOT + lvlOff + (size_t)(cbase + oc) * HW + hh * W + ww] = v;
            }
        }
    }
}

// ---------------------------------------------------------------------------
// FCOS grid locations.
// ---------------------------------------------------------------------------
__global__ void locations_kernel(float* __restrict__ out, size_t base)
{
    const int Wl[5] = {152, 76, 38, 19, 10};
    const int Sl[5] = {8, 16, 32, 64, 128};
    const int sizes[5] = {15200, 3800, 950, 247, 70};
    int idx = blockIdx.x * blockDim.x + threadIdx.x;
    if (idx >= 20267) return;
    int l = 0, t = idx;
    while (l < 4 && t >= sizes[l]) { t -= sizes[l]; l++; }
    int yy = t / Wl[l], xx = t - yy * Wl[l];
    out[base + (size_t)idx * 2 + 0] = (float)(xx * Sl[l] + Sl[l] / 2);
    out[base + (size_t)idx * 2 + 1] = (float)(yy * Sl[l] + Sl[l] / 2);
}

// ---------------------------------------------------------------------------
// Host orchestration
// ---------------------------------------------------------------------------
extern "C" void kernel_launch(void* const* d_in, const int* in_sizes, int n_in,
                              void* d_out, int out_size)
{
    const float* feats[5] = {
        (const float*)d_in[0], (const float*)d_in[1], (const float*)d_in[2],
        (const float*)d_in[3], (const float*)d_in[4]};
    const float* cls_w    = (const float*)d_in[5];
    const float* cls_b    = (const float*)d_in[6];
    const float* cls_gn_g = (const float*)d_in[7];
    const float* cls_gn_b = (const float*)d_in[8];
    const float* box_w    = (const float*)d_in[9];
    const float* box_b    = (const float*)d_in[10];
    const float* box_gn_g = (const float*)d_in[11];
    const float* box_gn_b = (const float*)d_in[12];
    const float* logits_w = (const float*)d_in[13];
    const float* logits_b = (const float*)d_in[14];
    const float* ctr_w    = (const float*)d_in[15];
    const float* ctr_b    = (const float*)d_in[16];
    const float* reg_w    = (const float*)d_in[17];
    const float* reg_b    = (const float*)d_in[18];
    const float* scales   = (const float*)d_in[19];

    float *buf0, *buf1, *buf2, *buf3, *stats, *aff;
    ull* wrs;
    cudaGetSymbolAddress((void**)&buf0, g_buf0);
    cudaGetSymbolAddress((void**)&buf1, g_buf1);
    cudaGetSymbolAddress((void**)&buf2, g_buf2);
    cudaGetSymbolAddress((void**)&buf3, g_buf3);
    cudaGetSymbolAddress((void**)&stats, g_stats);
    cudaGetSymbolAddress((void**)&aff, g_aff);
    cudaGetSymbolAddress((void**)&wrs, g_wrs);
    float* affA0 = aff;               // [2][2][2048]
    float* affS0 = aff + 2048;
    float* affA1 = aff + 4096;
    float* affS1 = aff + 6144;

    float* out = (float*)d_out;

    const int Hs[5] = {100, 50, 25, 13, 7};
    const int Ws[5] = {152, 76, 38, 19, 10};
    const size_t off85[5] = {0, 1292000, 1615000, 1695750, 1716745};
    const size_t TOT = 1722695;                 // 85 * 20267
    const size_t WLAY = (size_t)4 * 32 * 4608;  // ull per layer

    // one-time (per launch) weight reshape into dup-pair layout
    reshape_weights<<<(8*4*32*72*64 + 255) / 256, 256>>>(cls_w, box_w, wrs);

    for (int l = 0; l < 5; l++) {
        const int H = Hs[l], W = Ws[l], HW = H * W;
        dim3 grid((W + 15) / 16, (H + 7) / 8, 8 * 4);
        dim3 gridH((W + 7) / 8, (H + 7) / 8, 8);
        const float invCnt = 1.0f / (8.0f * (float)HW);

        // ---- cls tower (buf0/buf1, affine slot 0, layers 0-3) ----
        {
            const float* cur = feats[l];
            float* bufs[2] = {buf0, buf1};
            for (int i = 0; i < 4; i++) {
                const ull* wi = wrs + (size_t)i * WLAY;
                const float* bi = cls_b + i * 256;
                cudaMemsetAsync(stats, 0, 8 * 32 * 2 * sizeof(float), 0);
                if (i == 0)
                    conv256p<false><<<grid, 256>>>(cur, wi, bi, nullptr, nullptr,
                                                   bufs[i & 1], stats, H, W);
                else
                    conv256p<true><<<grid, 256>>>(cur, wi, bi, affA0, affS0,
                                                  bufs[i & 1], stats, H, W);
                gn_finalize<<<8, 256>>>(stats, cls_gn_g + i * 256, cls_gn_b + i * 256,
                                        affA0, affS0, invCnt);
                cur = bufs[i & 1];
            }
        }
        const float* ct = buf1;

        // ---- box tower (buf2/buf3, affine slot 1, layers 4-7) ----
        {
            const float* cur = feats[l];
            float* bufs[2] = {buf2, buf3};
            for (int i = 0; i < 4; i++) {
                const ull* wi = wrs + (size_t)(4 + i) * WLAY;
                const float* bi = box_b + i * 256;
                cudaMemsetAsync(stats, 0, 8 * 32 * 2 * sizeof(float), 0);
                if (i == 0)
                    conv256p<false><<<grid, 256>>>(cur, wi, bi, nullptr, nullptr,
                                                   bufs[i & 1], stats, H, W);
                else
                    conv256p<true><<<grid, 256>>>(cur, wi, bi, affA1, affS1,
                                                  bufs[i & 1], stats, H, W);
                gn_finalize<<<8, 256>>>(stats, box_gn_g + i * 256, box_gn_b + i * 256,
                                        affA1, affS1, invCnt);
                cur = bufs[i & 1];
            }
        }
        const float* bt = buf3;

        // ---- heads: logits(80)@c0, reg(4)@c80 (exp), ctr(1)@c84 ----
        conv_head<<<gridH, 256>>>(ct, logits_w, logits_b, affA0, affS0,
                                  out, off85[l], TOT, 0, 80, H, W, 0, scales, l);
        conv_head<<<gridH, 256>>>(bt, reg_w, reg_b, affA1, affS1,
                                  out, off85[l], TOT, 80, 4, H, W, 1, scales, l);
        conv_head<<<gridH, 256>>>(ct, ctr_w, ctr_b, affA0, affS0,
                                  out, off85[l], TOT, 84, 1, H, W, 0, scales, l);
    }

    locations_kernel<<<(20267 + 255) / 256, 256>>>(out, (size_t)8 * TOT);
}

// round 14
// speedup vs baseline: 2.2935x; 1.8412x over previous
#include <cuda_runtime.h>
#include <cuda_bf16.h>
#include <math.h>
#include <stdint.h>

// ---------------------------------------------------------------------------
// FCOS head. Tower convs (256->256, 3x3) as implicit GEMM on warp-level
// mma.sync.m16n8k16 bf16 (compute_103-safe; HMMA units) with 3-term hi/lo
// bf16 split for fp32-grade accuracy:
//   x*w ~= xh*wh + xh*wl + xl*wh   (lo*lo term ~2^-18, dropped)
// Per CTA: D[128 oc x 128 px] over K = 9 shifts x 256 ic (36 chunks of 64).
// GN stats via atomics in epilogue; GN apply + ReLU fused into next conv's
// B-tile gather. Heads (80/4/1 oc) scalar fp32 into final output layout.
// ---------------------------------------------------------------------------

#define MAXBUF (8*256*15200)

__device__ float g_buf0[MAXBUF];
__device__ float g_buf1[MAXBUF];
__device__ float g_buf2[MAXBUF];
__device__ float g_buf3[MAXBUF];
__device__ float g_stats[8*32*2];
__device__ float g_aff[2][2][8*256];                    // [slot][A|S][b*256+c]
__device__ __nv_bfloat16 g_wtc[8u*2u*36u*16384u];       // 8 layers x 2 ocTiles x 36 chunks x (hi 8192 | lo 8192)

__device__ __forceinline__ uint32_t smem_u32(const void* p) {
    uint32_t a;
    asm("{ .reg .u64 t; cvta.to.shared.u64 t, %1; cvt.u32.u64 %0, t; }"
        : "=r"(a) : "l"(p));
    return a;
}
__device__ __forceinline__ void ldsm_x4(uint32_t& r0, uint32_t& r1,
                                        uint32_t& r2, uint32_t& r3, uint32_t addr) {
    asm volatile("ldmatrix.sync.aligned.m8n8.x4.shared.b16 {%0,%1,%2,%3}, [%4];"
                 : "=r"(r0), "=r"(r1), "=r"(r2), "=r"(r3) : "r"(addr));
}
__device__ __forceinline__ void mma_bf16(float* c, uint32_t a0, uint32_t a1,
                                         uint32_t a2, uint32_t a3,
                                         uint32_t b0, uint32_t b1) {
    asm volatile(
        "mma.sync.aligned.m16n8k16.row.col.f32.bf16.bf16.f32 "
        "{%0,%1,%2,%3}, {%4,%5,%6,%7}, {%8,%9}, {%0,%1,%2,%3};"
        : "+f"(c[0]), "+f"(c[1]), "+f"(c[2]), "+f"(c[3])
        : "r"(a0), "r"(a1), "r"(a2), "r"(a3), "r"(b0), "r"(b1));
}

// smem tile geometry: rows of 64 bf16 padded to 144 B (16B-aligned rows,
// conflict-free ldmatrix: row r -> banks 4r..4r+3).
#define PITCHB 144

// ---------------------------------------------------------------------------
// Weight reshape: fp32 w[lay][oc][ic*9+k] -> plain bf16 hi/lo tiles:
// g_wtc[((lay*2+ot)*36+chunk)*16384 + plane*8192 + oc_r*64 + ic_c]
// chunk = k*4 + icc (k = shift 0..8, icc = ic-chunk of 64). lay 0-3 cls, 4-7 box.
// ---------------------------------------------------------------------------
__global__ void reshape_wtc(const float* __restrict__ cls_w,
                            const float* __restrict__ box_w,
                            __nv_bfloat16* __restrict__ out)
{
    unsigned idx = blockIdx.x * blockDim.x + threadIdx.x;   // 4,718,592
    if (idx >= 8u*2u*36u*8192u) return;
    unsigned e = idx & 8191u;
    unsigned oc_r = e >> 6, ic_c = e & 63u;
    unsigned t = idx >> 13;
    unsigned chunk = t % 36u; t /= 36u;
    unsigned ot = t & 1u;  unsigned lay = t >> 1;
    unsigned k = chunk >> 2, icc = chunk & 3u;
    const float* src = (lay < 4) ? cls_w : box_w;
    unsigned l = lay & 3u;
    unsigned oc = ot * 128u + oc_r;
    unsigned ic = icc * 64u + ic_c;
    float w = src[(size_t)l * 256u * 2304u + (size_t)oc * 2304u + ic * 9u + k];
    __nv_bfloat16 hi = __float2bfloat16(w);
    __nv_bfloat16 lo = __float2bfloat16(w - __bfloat162float(hi));
    size_t base = ((size_t)(lay * 2u + ot) * 36u + chunk) * 16384u;
    out[base + oc_r * 64u + ic_c] = hi;
    out[base + 8192u + oc_r * 64u + ic_c] = lo;
}

// ---------------------------------------------------------------------------
// Tower conv on mma.sync. Block: 256 threads (8 warps),
// grid (ceil(HW/128), B=8, ot=2). Warp = 64 oc x 32 px.
// ---------------------------------------------------------------------------
template<bool AFF>
__global__ __launch_bounds__(256, 2)
void conv_mma(const float* __restrict__ x, const __nv_bfloat16* __restrict__ wt,
              const float* __restrict__ bias, const float* __restrict__ affA,
              const float* __restrict__ affS, float* __restrict__ y,
              float* __restrict__ stats, int H, int W)
{
    extern __shared__ char dsm[];
    const int HW = H * W;
    const int b  = blockIdx.y, ot = blockIdx.z;
    const int p0 = blockIdx.x << 7;
    const int tid = threadIdx.x, wid = tid >> 5, lane = tid & 31;

    uint32_t sraw = smem_u32(dsm);
    uint32_t sb = (sraw + 1023u) & ~1023u;
    char* base = dsm + (sb - sraw);
    // planes: Ahi 0, Alo 18432, Bhi 36864, Blo 55296 (each 128 rows x 144 B)
    const uint32_t uAhi = sb, uAlo = sb + 18432, uBhi = sb + 36864, uBlo = sb + 55296;
    char* pBhi = base + 36864;
    char* pBlo = base + 55296;
    float* s_out = (float*)base;               // 128 x 132 fp32 (epilogue reuse)

    // B geometry: pixel j per thread (two threads per px: pb = ic half)
    const int j = tid & 127;
    const int pb = tid >> 7;
    const int p = p0 + j;
    const bool inimg = p < HW;
    const int hh = p / W;
    const int ww = p - hh * W;
    const float* xb = x + ((size_t)b << 8) * HW;

    // warp tile position
    const int warp_m = wid & 1;     // 2 x 64 oc
    const int warp_n = wid >> 1;    // 4 x 32 px
    // ldmatrix lane addressing
    const int a_row = lane & 15, a_k8 = lane >> 4;
    const int b_sel = lane >> 3, b_row = lane & 7;

    float acc[4][4][4];
    #pragma unroll
    for (int mt = 0; mt < 4; mt++)
        #pragma unroll
        for (int nt = 0; nt < 4; nt++)
            #pragma unroll
            for (int q = 0; q < 4; q++) acc[mt][nt][q] = 0.f;

    for (int chunk = 0; chunk < 36; chunk++) {
        // ---- A fill: 2 planes x 1024 x 16B, rows repadded 128B -> 144B ----
        {
            const uint4* ws = (const uint4*)(wt + ((size_t)(ot * 36 + chunk) << 14));
            #pragma unroll
            for (int pl = 0; pl < 2; pl++) {
                char* dstp = base + pl * 18432;
                const uint4* srcp = ws + pl * 1024;
                #pragma unroll
                for (int i = 0; i < 4; i++) {
                    int u = tid + (i << 8);
                    int row = u >> 3, c8 = u & 7;
                    *(uint4*)(dstp + row * PITCHB + (c8 << 4)) = srcp[u];
                }
            }
        }
        // ---- B fill: gather shifted x, affine+relu, hi/lo split ----
        {
            const int k  = chunk >> 2;
            const int dh = k / 3 - 1, dw = k - (k / 3) * 3 - 1;
            const int ic0 = (chunk & 3) << 6;
            const int h2 = hh + dh, w2 = ww + dw;
            const bool valid = inimg && (unsigned)h2 < (unsigned)H && (unsigned)w2 < (unsigned)W;
            const int off = p + dh * W + dw;
            #pragma unroll 4
            for (int it = 0; it < 16; it++) {
                int ic_c = (pb << 5) + (it << 1);     // 0..62 within chunk
                int ic   = ic0 + ic_c;
                float v0 = 0.f, v1 = 0.f;
                if (valid) {
                    v0 = __ldg(xb + (size_t)ic * HW + off);
                    v1 = __ldg(xb + (size_t)(ic + 1) * HW + off);
                    if (AFF) {
                        v0 = fmaxf(fmaf(affA[(b << 8) + ic],     v0, affS[(b << 8) + ic]),     0.f);
                        v1 = fmaxf(fmaf(affA[(b << 8) + ic + 1], v1, affS[(b << 8) + ic + 1]), 0.f);
                    }
                }
                __nv_bfloat16 h0 = __float2bfloat16(v0);
                __nv_bfloat16 h1 = __float2bfloat16(v1);
                __nv_bfloat16 l0 = __float2bfloat16(v0 - __bfloat162float(h0));
                __nv_bfloat16 l1 = __float2bfloat16(v1 - __bfloat162float(h1));
                *(__nv_bfloat162*)(pBhi + j * PITCHB + ic_c * 2) = __nv_bfloat162(h0, h1);
                *(__nv_bfloat162*)(pBlo + j * PITCHB + ic_c * 2) = __nv_bfloat162(l0, l1);
            }
        }
        __syncthreads();

        // ---- compute: 4 k16-steps over the 64-ic chunk ----
        #pragma unroll
        for (int ks = 0; ks < 4; ks++) {
            // B frags: matrix order [ntE k0, ntE k8, ntO k0, ntO k8]
            uint32_t bh[8], bl[8];
            #pragma unroll
            for (int half = 0; half < 2; half++) {
                uint32_t nrow = warp_n * 32 + half * 16 + ((b_sel >> 1) << 3) + b_row;
                uint32_t koff = (ks << 4) + ((b_sel & 1) << 3);
                ldsm_x4(bh[half*4+0], bh[half*4+1], bh[half*4+2], bh[half*4+3],
                        uBhi + nrow * PITCHB + koff * 2);
                ldsm_x4(bl[half*4+0], bl[half*4+1], bl[half*4+2], bl[half*4+3],
                        uBlo + nrow * PITCHB + koff * 2);
            }
            #pragma unroll
            for (int mt = 0; mt < 4; mt++) {
                uint32_t arow = warp_m * 64 + mt * 16 + a_row;
                uint32_t koff = (ks << 4) + (a_k8 << 3);
                uint32_t ah0, ah1, ah2, ah3, al0, al1, al2, al3;
                ldsm_x4(ah0, ah1, ah2, ah3, uAhi + arow * PITCHB + koff * 2);
                ldsm_x4(al0, al1, al2, al3, uAlo + arow * PITCHB + koff * 2);
                #pragma unroll
                for (int nt = 0; nt < 4; nt++) {
                    uint32_t b0h = bh[(nt >> 1) * 4 + ((nt & 1) << 1)];
                    uint32_t b1h = bh[(nt >> 1) * 4 + ((nt & 1) << 1) + 1];
                    uint32_t b0l = bl[(nt >> 1) * 4 + ((nt & 1) << 1)];
                    uint32_t b1l = bl[(nt >> 1) * 4 + ((nt & 1) << 1) + 1];
                    mma_bf16(acc[mt][nt], ah0, ah1, ah2, ah3, b0h, b1h);
                    mma_bf16(acc[mt][nt], ah0, ah1, ah2, ah3, b0l, b1l);
                    mma_bf16(acc[mt][nt], al0, al1, al2, al3, b0h, b1h);
                }
            }
        }
        __syncthreads();
    }

    // ---- epilogue: acc + bias -> s_out -> stats -> coalesced store ----
    #pragma unroll
    for (int mt = 0; mt < 4; mt++) {
        int r1 = warp_m * 64 + mt * 16 + (lane >> 2);
        int r2 = r1 + 8;
        float bv1 = __ldg(bias + ot * 128 + r1);
        float bv2 = __ldg(bias + ot * 128 + r2);
        #pragma unroll
        for (int nt = 0; nt < 4; nt++) {
            int cb = warp_n * 32 + nt * 8 + ((lane & 3) << 1);
            s_out[r1 * 132 + cb]     = acc[mt][nt][0] + bv1;
            s_out[r1 * 132 + cb + 1] = acc[mt][nt][1] + bv1;
            s_out[r2 * 132 + cb]     = acc[mt][nt][2] + bv2;
            s_out[r2 * 132 + cb + 1] = acc[mt][nt][3] + bv2;
        }
    }
    __syncthreads();

    // stats: thread t handles half a row (row = t>>1, 64 cols)
    {
        int row = tid >> 1, half = tid & 1;
        float lsum = 0.f, lsq = 0.f;
        #pragma unroll 8
        for (int c = 0; c < 64; c++) {
            int col = (half << 6) + c;
            if (p0 + col < HW) {
                float v = s_out[row * 132 + col];
                lsum += v; lsq += v * v;
            }
        }
        #pragma unroll
        for (int o = 1; o <= 8; o <<= 1) {
            lsum += __shfl_xor_sync(0xffffffffu, lsum, o);
            lsq  += __shfl_xor_sync(0xffffffffu, lsq,  o);
        }
        if ((lane & 15) == 0) {
            int g = ot * 16 + (row >> 3);
            atomicAdd(&stats[(b * 32 + g) * 2 + 0], lsum);
            atomicAdd(&stats[(b * 32 + g) * 2 + 1], lsq);
        }
    }
    // coalesced store to y
    for (int i = 0; i < 64; i++) {
        int idx  = tid + (i << 8);
        int oc_r = idx >> 7, jj = idx & 127;
        int pp = p0 + jj;
        if (pp < HW)
            y[(((size_t)b << 8) + (ot << 7) + oc_r) * HW + pp] = s_out[oc_r * 132 + jj];
    }
}

// ---------------------------------------------------------------------------
// GN finalize: stats -> per-channel affine (a, s).
// ---------------------------------------------------------------------------
__global__ void gn_finalize(const float* __restrict__ stats,
                            const float* __restrict__ gamma,
                            const float* __restrict__ beta,
                            float* __restrict__ affA, float* __restrict__ affS,
                            float invCnt)
{
    int b = blockIdx.x;
    int c = threadIdx.x;
    int g = c >> 3;
    float sum = stats[(b * 32 + g) * 2 + 0];
    float sq  = stats[(b * 32 + g) * 2 + 1];
    float m   = sum * invCnt;
    float var = fmaf(sq, invCnt, -m * m);
    float rstd = rsqrtf(var + 1e-5f);
    float a = gamma[c] * rstd;
    affA[b * 256 + c] = a;
    affS[b * 256 + c] = fmaf(-m, a, beta[c]);
}

// ---------------------------------------------------------------------------
// Head conv: IC=256, OC in {80,1,4}. Affine+relu input. Direct final layout.
// ---------------------------------------------------------------------------
__global__ __launch_bounds__(256) void conv_head(
    const float* __restrict__ x, const float* __restrict__ w,
    const float* __restrict__ bias,
    const float* __restrict__ affA, const float* __restrict__ affS,
    float* __restrict__ out, size_t lvlOff, size_t TOT, int cbase,
    int OC, int H, int W, int doExp, const float* __restrict__ scales, int lvl)
{
    const int HW = H * W;
    const int b  = blockIdx.z;
    const int h0 = blockIdx.y << 3, w0 = blockIdx.x << 3;
    const int tid  = threadIdx.x;
    const int lane = tid & 3;
    const int pp   = tid >> 2;
    const int ph = pp >> 3, pw = pp & 7;

    __shared__ float s_in[8][10][12];
    __shared__ float s_w[8][9][80];

    float acc[20];
    const int noc = (OC + 3) >> 2;
    #pragma unroll
    for (int jj = 0; jj < 20; jj++) acc[jj] = 0.f;

    const float* xb = x + (size_t)b * 256 * HW;
    const float* aA = affA + b * 256;
    const float* aS = affS + b * 256;

    for (int c0 = 0; c0 < 256; c0 += 8) {
        for (int idx = tid; idx < 800; idx += 256) {
            int ic = idx / 100; int rr = idx - ic * 100;
            int r = rr / 10;    int c  = rr - r * 10;
            int ih = h0 - 1 + r, iw = w0 - 1 + c;
            float v = 0.f;
            if ((unsigned)ih < (unsigned)H && (unsigned)iw < (unsigned)W) {
                v = xb[(size_t)(c0 + ic) * HW + ih * W + iw];
                v = fmaxf(fmaf(aA[c0 + ic], v, aS[c0 + ic]), 0.f);
            }
            s_in[ic][r][c] = v;
        }
        int nw = OC * 72;
        for (int idx = tid; idx < nw; idx += 256) {
            int oc = idx / 72; int rem = idx - oc * 72;
            int ic = rem / 9;  int k   = rem - ic * 9;
            s_w[ic][k][oc] = w[(size_t)oc * 2304 + (c0 + ic) * 9 + k];
        }
        __syncthreads();

        #pragma unroll 2
        for (int ic = 0; ic < 8; ic++) {
            #pragma unroll
            for (int kh = 0; kh < 3; kh++) {
                #pragma unroll
                for (int kw = 0; kw < 3; kw++) {
                    float xv = s_in[ic][ph + kh][pw + kw];
                    int k = kh * 3 + kw;
                    for (int jj = 0; jj < noc; jj++)
                        acc[jj] = fmaf(xv, s_w[ic][k][(jj << 2) + lane], acc[jj]);
                }
            }
        }
        __syncthreads();
    }

    int hh = h0 + ph, ww = w0 + pw;
    if (hh < H && ww < W) {
        float sc = doExp ? scales[lvl] : 0.f;
        for (int jj = 0; jj < noc; jj++) {
            int oc = (jj << 2) + lane;
            if (oc < OC) {
                float v = acc[jj] + bias[oc];
                if (doExp) v = expf(sc * v);
                out[(size_t)b * TOT + lvlOff + (size_t)(cbase + oc) * HW + hh * W + ww] = v;
            }
        }
    }
}

// ---------------------------------------------------------------------------
// FCOS grid locations.
// ---------------------------------------------------------------------------
__global__ void locations_kernel(float* __restrict__ out, size_t base)
{
    const int Wl[5] = {152, 76, 38, 19, 10};
    const int Sl[5] = {8, 16, 32, 64, 128};
    const int sizes[5] = {15200, 3800, 950, 247, 70};
    int idx = blockIdx.x * blockDim.x + threadIdx.x;
    if (idx >= 20267) return;
    int l = 0, t = idx;
    while (l < 4 && t >= sizes[l]) { t -= sizes[l]; l++; }
    int yy = t / Wl[l], xx = t - yy * Wl[l];
    out[base + (size_t)idx * 2 + 0] = (float)(xx * Sl[l] + Sl[l] / 2);
    out[base + (size_t)idx * 2 + 1] = (float)(yy * Sl[l] + Sl[l] / 2);
}

// ---------------------------------------------------------------------------
// Host orchestration
// ---------------------------------------------------------------------------
extern "C" void kernel_launch(void* const* d_in, const int* in_sizes, int n_in,
                              void* d_out, int out_size)
{
    const float* feats[5] = {
        (const float*)d_in[0], (const float*)d_in[1], (const float*)d_in[2],
        (const float*)d_in[3], (const float*)d_in[4]};
    const float* cls_w    = (const float*)d_in[5];
    const float* cls_b    = (const float*)d_in[6];
    const float* cls_gn_g = (const float*)d_in[7];
    const float* cls_gn_b = (const float*)d_in[8];
    const float* box_w    = (const float*)d_in[9];
    const float* box_b    = (const float*)d_in[10];
    const float* box_gn_g = (const float*)d_in[11];
    const float* box_gn_b = (const float*)d_in[12];
    const float* logits_w = (const float*)d_in[13];
    const float* logits_b = (const float*)d_in[14];
    const float* ctr_w    = (const float*)d_in[15];
    const float* ctr_b    = (const float*)d_in[16];
    const float* reg_w    = (const float*)d_in[17];
    const float* reg_b    = (const float*)d_in[18];
    const float* scales   = (const float*)d_in[19];

    float *buf0, *buf1, *buf2, *buf3, *stats, *aff;
    __nv_bfloat16* wtc;
    cudaGetSymbolAddress((void**)&buf0, g_buf0);
    cudaGetSymbolAddress((void**)&buf1, g_buf1);
    cudaGetSymbolAddress((void**)&buf2, g_buf2);
    cudaGetSymbolAddress((void**)&buf3, g_buf3);
    cudaGetSymbolAddress((void**)&stats, g_stats);
    cudaGetSymbolAddress((void**)&aff, g_aff);
    cudaGetSymbolAddress((void**)&wtc, g_wtc);
    float* affA0 = aff;
    float* affS0 = aff + 2048;
    float* affA1 = aff + 4096;
    float* affS1 = aff + 6144;

    float* out = (float*)d_out;

    const int Hs[5] = {100, 50, 25, 13, 7};
    const int Ws[5] = {152, 76, 38, 19, 10};
    const size_t off85[5] = {0, 1292000, 1615000, 1695750, 1716745};
    const size_t TOT = 1722695;
    const size_t WLAY = (size_t)2 * 36 * 16384;      // bf16 per layer
    const int DYN = 73728 + 1024;

    cudaFuncSetAttribute(conv_mma<false>, cudaFuncAttributeMaxDynamicSharedMemorySize, DYN);
    cudaFuncSetAttribute(conv_mma<true>,  cudaFuncAttributeMaxDynamicSharedMemorySize, DYN);

    // one-time weight reshape into bf16 hi/lo tiles
    reshape_wtc<<<(8*2*36*8192 + 255) / 256, 256>>>(cls_w, box_w, wtc);

    for (int l = 0; l < 5; l++) {
        const int H = Hs[l], W = Ws[l], HW = H * W;
        const int ntiles = (HW + 127) / 128;
        dim3 grid(ntiles, 8, 2);
        dim3 gridH((W + 7) / 8, (H + 7) / 8, 8);
        const float invCnt = 1.0f / (8.0f * (float)HW);

        // ---- cls tower (layers 0-3, affine slot 0) ----
        {
            const float* cur = feats[l];
            float* bufs[2] = {buf0, buf1};
            for (int i = 0; i < 4; i++) {
                const __nv_bfloat16* wi = wtc + (size_t)i * WLAY;
                const float* bi = cls_b + i * 256;
                cudaMemsetAsync(stats, 0, 8 * 32 * 2 * sizeof(float), 0);
                if (i == 0)
                    conv_mma<false><<<grid, 256, DYN>>>(cur, wi, bi, nullptr, nullptr,
                                                        bufs[i & 1], stats, H, W);
                else
                    conv_mma<true><<<grid, 256, DYN>>>(cur, wi, bi, affA0, affS0,
                                                       bufs[i & 1], stats, H, W);
                gn_finalize<<<8, 256>>>(stats, cls_gn_g + i * 256, cls_gn_b + i * 256,
                                        affA0, affS0, invCnt);
                cur = bufs[i & 1];
            }
        }
        const float* ct = buf1;

        // ---- box tower (layers 4-7, affine slot 1) ----
        {
            const float* cur = feats[l];
            float* bufs[2] = {buf2, buf3};
            for (int i = 0; i < 4; i++) {
                const __nv_bfloat16* wi = wtc + (size_t)(4 + i) * WLAY;
                const float* bi = box_b + i * 256;
                cudaMemsetAsync(stats, 0, 8 * 32 * 2 * sizeof(float), 0);
                if (i == 0)
                    conv_mma<false><<<grid, 256, DYN>>>(cur, wi, bi, nullptr, nullptr,
                                                        bufs[i & 1], stats, H, W);
                else
                    conv_mma<true><<<grid, 256, DYN>>>(cur, wi, bi, affA1, affS1,
                                                       bufs[i & 1], stats, H, W);
                gn_finalize<<<8, 256>>>(stats, box_gn_g + i * 256, box_gn_b + i * 256,
                                        affA1, affS1, invCnt);
                cur = bufs[i & 1];
            }
        }
        const float* bt = buf3;

        // ---- heads ----
        conv_head<<<gridH, 256>>>(ct, logits_w, logits_b, affA0, affS0,
                                  out, off85[l], TOT, 0, 80, H, W, 0, scales, l);
        conv_head<<<gridH, 256>>>(bt, reg_w, reg_b, affA1, affS1,
                                  out, off85[l], TOT, 80, 4, H, W, 1, scales, l);
        conv_head<<<gridH, 256>>>(ct, ctr_w, ctr_b, affA0, affS0,
                                  out, off85[l], TOT, 84, 1, H, W, 0, scales, l);
    }

    locations_kernel<<<(20267 + 255) / 256, 256>>>(out, (size_t)8 * TOT);
}